// round 6
// baseline (speedup 1.0000x reference)
#include <cuda_runtime.h>
#include <cuda_bf16.h>
#include <cstdint>

#define NN 50000
#define EE 600000

// ---------------- scratch ----------------
__device__ int   g_is32;
__device__ int   g_deg[NN];
__device__ int   g_off[NN + 1];
__device__ int   g_cur[NN];
__device__ int   g_csr[EE];
__device__ float g_p1[(size_t)NN * 128];
__device__ float g_q1[(size_t)NN * 128];
__device__ float g_h [(size_t)NN * 128];
__device__ float g_p2[(size_t)NN * 64];
__device__ float g_q2[(size_t)NN * 64];

// ---------------- dtype probe + CSR ----------------
__global__ void probe_kernel(const long long* __restrict__ ei, int count, int N,
                             int* __restrict__ flag) {
    int i = blockIdx.x * blockDim.x + threadIdx.x;
    int stride = gridDim.x * blockDim.x;
    bool bad = false;
    for (; i < count; i += stride) {
        long long v = ei[i];
        bad |= (v < 0 || v >= (long long)N);
    }
    if (__any_sync(0xFFFFFFFF, bad) && (threadIdx.x & 31) == 0)
        *flag = 1;
}
__device__ __forceinline__ int load_idx(const void* ei, int pos, int is32) {
    if (is32) return ((const int*)ei)[pos];
    return (int)((const long long*)ei)[pos];
}
__global__ void hist_kernel(const void* __restrict__ ei, int E, int N,
                            int* __restrict__ deg) {
    int i = blockIdx.x * blockDim.x + threadIdx.x;
    if (i >= E) return;
    int d = load_idx(ei, E + i, g_is32);
    if ((unsigned)d < (unsigned)N) atomicAdd(&deg[d], 1);
}
__global__ void scan_kernel(const int* __restrict__ deg, int* __restrict__ off,
                            int* __restrict__ cur, int n) {
    __shared__ int part[1024];
    int t = threadIdx.x;
    int chunk = (n + 1023) / 1024;
    int begin = t * chunk, end = begin + chunk;
    if (end > n) end = n;
    int s = 0;
    for (int i = begin; i < end; i++) s += deg[i];
    part[t] = s;
    __syncthreads();
    for (int d = 1; d < 1024; d <<= 1) {
        int v = (t >= d) ? part[t - d] : 0;
        __syncthreads();
        part[t] += v;
        __syncthreads();
    }
    int run = (t == 0) ? 0 : part[t - 1];
    for (int i = begin; i < end; i++) { off[i] = run; cur[i] = run; run += deg[i]; }
    if (t == 1023) off[n] = part[1023];
}
__global__ void scatter_kernel(const void* __restrict__ ei, int E, int N,
                               int* __restrict__ cur, int* __restrict__ csr) {
    int i = blockIdx.x * blockDim.x + threadIdx.x;
    if (i >= E) return;
    int is32 = g_is32;
    int s = load_idx(ei, i, is32);
    int d = load_idx(ei, E + i, is32);
    if ((unsigned)d >= (unsigned)N || (unsigned)s >= (unsigned)N) return;
    int pos = atomicAdd(&cur[d], 1);
    if ((unsigned)pos < (unsigned)EE) csr[pos] = s;
}

// ---------------- mma.sync helpers ----------------
__device__ __forceinline__ uint32_t smem_u32(const void* p) {
    uint32_t a;
    asm("{ .reg .u64 t; cvta.to.shared.u64 t, %1; cvt.u32.u64 %0, t; }" : "=r"(a) : "l"(p));
    return a;
}
#define LDSM_X4(r0, r1, r2, r3, addr)                                          \
    asm volatile("ldmatrix.sync.aligned.m8n8.x4.shared.b16 {%0,%1,%2,%3}, [%4];" \
                 : "=r"(r0), "=r"(r1), "=r"(r2), "=r"(r3) : "r"(addr))
#define MMA16816(d, a, b)                                                      \
    asm volatile("mma.sync.aligned.m16n8k16.row.col.f32.bf16.bf16.f32 "        \
                 "{%0,%1,%2,%3}, {%4,%5,%6,%7}, {%8,%9}, {%0,%1,%2,%3};"       \
                 : "+f"((d)[0]), "+f"((d)[1]), "+f"((d)[2]), "+f"((d)[3])       \
                 : "r"((a)[0]), "r"((a)[1]), "r"((a)[2]), "r"((a)[3]),          \
                   "r"((b)[0]), "r"((b)[1]))

__device__ __forceinline__ void split_bf16(float v, __nv_bfloat16& hi, __nv_bfloat16& lo) {
    hi = __float2bfloat16(v);
    lo = __float2bfloat16(v - __bfloat162float(hi));
}

// ---------------- dual GEMM: out0 = A@W0, out1 = A@W1 ----------------
// 3-pass bf16 split: D = Ah*Bh + Ah*Bl + Al*Bh  (fp32 accum).
template <int NCOL>
__global__ void __launch_bounds__(512, 1)
mma_gemm(const float* __restrict__ A, const float* __restrict__ W0,
         const float* __restrict__ W1, float* __restrict__ out0,
         float* __restrict__ out1, int M) {
    constexpr int NT   = 2 * NCOL;
    constexpr int LDK  = 136;
    constexpr int A_H  = 0;
    constexpr int A_L  = 128 * LDK;
    constexpr int B_H  = 2 * 128 * LDK;
    constexpr int B_L  = B_H + NT * LDK;
    constexpr int WC   = NT / 4;
    constexpr int NTL  = WC / 8;

    extern __shared__ __nv_bfloat16 sm[];
    const uint32_t sbase = smem_u32(sm);
    const int tid  = threadIdx.x;
    const int wid  = tid >> 5, lane = tid & 31;
    const int brow = blockIdx.x * 128;

    for (int i = tid; i < 128 * 32; i += 512) {
        int row = i >> 5, c4 = (i & 31) << 2;
        float4 v = make_float4(0.f, 0.f, 0.f, 0.f);
        if (brow + row < M)
            v = *(const float4*)(A + (size_t)(brow + row) * 128 + c4);
        __nv_bfloat16 h0, l0, h1, l1, h2, l2, h3, l3;
        split_bf16(v.x, h0, l0); split_bf16(v.y, h1, l1);
        split_bf16(v.z, h2, l2); split_bf16(v.w, h3, l3);
        int o = row * LDK + c4;
        *(__nv_bfloat162*)(sm + A_H + o)     = __nv_bfloat162(h0, h1);
        *(__nv_bfloat162*)(sm + A_H + o + 2) = __nv_bfloat162(h2, h3);
        *(__nv_bfloat162*)(sm + A_L + o)     = __nv_bfloat162(l0, l1);
        *(__nv_bfloat162*)(sm + A_L + o + 2) = __nv_bfloat162(l2, l3);
    }
    for (int i = tid; i < NT * 128; i += 512) {
        int k = i / NT, n = i % NT;
        float v = (n < NCOL) ? W0[k * NCOL + n] : W1[k * NCOL + (n - NCOL)];
        __nv_bfloat16 h, l;
        split_bf16(v, h, l);
        sm[B_H + n * LDK + k] = h;
        sm[B_L + n * LDK + k] = l;
    }
    __syncthreads();

    const int r0 = (wid >> 2) * 32;
    const int c0 = (wid & 3) * WC;
    const uint32_t frag_off = (uint32_t)((lane & 15) * LDK + (lane >> 4) * 8) * 2;

    float acc[2][NTL][4];
#pragma unroll
    for (int mt = 0; mt < 2; mt++)
#pragma unroll
        for (int nt = 0; nt < NTL; nt++)
#pragma unroll
            for (int j = 0; j < 4; j++) acc[mt][nt][j] = 0.f;

    const int APASS[3] = {A_H, A_H, A_L};
    const int BPASS[3] = {B_H, B_L, B_H};
#pragma unroll
    for (int pass = 0; pass < 3; pass++) {
        const uint32_t abase = sbase + (uint32_t)APASS[pass] * 2 + frag_off;
        const uint32_t bbase = sbase + (uint32_t)BPASS[pass] * 2 + frag_off;
#pragma unroll
        for (int ks = 0; ks < 8; ks++) {
            uint32_t a[2][4];
#pragma unroll
            for (int mt = 0; mt < 2; mt++)
                LDSM_X4(a[mt][0], a[mt][1], a[mt][2], a[mt][3],
                        abase + (uint32_t)((r0 + mt * 16) * LDK + ks * 16) * 2);
            uint32_t b[NTL][2];
#pragma unroll
            for (int np = 0; np < NTL / 2; np++) {
                uint32_t q0, q1, q2, q3;
                LDSM_X4(q0, q1, q2, q3,
                        bbase + (uint32_t)((c0 + np * 16) * LDK + ks * 16) * 2);
                b[2 * np][0] = q0; b[2 * np][1] = q2;
                b[2 * np + 1][0] = q1; b[2 * np + 1][1] = q3;
            }
#pragma unroll
            for (int mt = 0; mt < 2; mt++)
#pragma unroll
                for (int nt = 0; nt < NTL; nt++)
                    MMA16816(acc[mt][nt], a[mt], b[nt]);
        }
    }

    float* dst = (c0 < NCOL) ? out0 : out1;
    const int ncoff = (c0 < NCOL) ? c0 : (c0 - NCOL);
#pragma unroll
    for (int mt = 0; mt < 2; mt++) {
        int rlo = brow + r0 + mt * 16 + (lane >> 2);
        int rhi = rlo + 8;
#pragma unroll
        for (int nt = 0; nt < NTL; nt++) {
            int col = ncoff + nt * 8 + (lane & 3) * 2;
            if (rlo < M)
                *(float2*)(dst + (size_t)rlo * NCOL + col) =
                    make_float2(acc[mt][nt][0], acc[mt][nt][1]);
            if (rhi < M)
                *(float2*)(dst + (size_t)rhi * NCOL + col) =
                    make_float2(acc[mt][nt][2], acc[mt][nt][3]);
        }
    }
}

// ---------------- aggregation: float4, 4-way unrolled, node-range [v0,v1) ----------------
template <int D, bool RELU>
__global__ void agg_kernel(const float* __restrict__ p, const float* __restrict__ q,
                           const float* __restrict__ bias,
                           const int* __restrict__ off, const int* __restrict__ csr,
                           float* __restrict__ out, int v0, int v1) {
    const int tx = threadIdx.x;             // [0, D/4)
    const int v = v0 + blockIdx.x * blockDim.y + threadIdx.y;
    if (v >= v1) return;
    const int s = off[v], e = off[v + 1];

    float4 a0 = make_float4(0.f, 0.f, 0.f, 0.f);
    float4 a1 = make_float4(0.f, 0.f, 0.f, 0.f);
    float4 a2 = make_float4(0.f, 0.f, 0.f, 0.f);
    float4 a3 = make_float4(0.f, 0.f, 0.f, 0.f);
    int i = s;
    for (; i + 4 <= e; i += 4) {
        int u0 = __ldg(&csr[i]),     u1 = __ldg(&csr[i + 1]);
        int u2 = __ldg(&csr[i + 2]), u3 = __ldg(&csr[i + 3]);
        float4 x0 = *(const float4*)(p + (size_t)u0 * D + tx * 4);
        float4 x1 = *(const float4*)(p + (size_t)u1 * D + tx * 4);
        float4 x2 = *(const float4*)(p + (size_t)u2 * D + tx * 4);
        float4 x3 = *(const float4*)(p + (size_t)u3 * D + tx * 4);
        a0.x += x0.x; a0.y += x0.y; a0.z += x0.z; a0.w += x0.w;
        a1.x += x1.x; a1.y += x1.y; a1.z += x1.z; a1.w += x1.w;
        a2.x += x2.x; a2.y += x2.y; a2.z += x2.z; a2.w += x2.w;
        a3.x += x3.x; a3.y += x3.y; a3.z += x3.z; a3.w += x3.w;
    }
    for (; i < e; i++) {
        int u0 = __ldg(&csr[i]);
        float4 x0 = *(const float4*)(p + (size_t)u0 * D + tx * 4);
        a0.x += x0.x; a0.y += x0.y; a0.z += x0.z; a0.w += x0.w;
    }
    a0.x += a1.x + a2.x + a3.x;
    a0.y += a1.y + a2.y + a3.y;
    a0.z += a1.z + a2.z + a3.z;
    a0.w += a1.w + a2.w + a3.w;

    const float inv = (e > s) ? 1.f / (float)(e - s) : 0.f;
    float4 bb = *(const float4*)(bias + tx * 4);
    float4 qq = *(const float4*)(q + (size_t)v * D + tx * 4);
    float4 r;
    r.x = a0.x * inv + bb.x + qq.x;
    r.y = a0.y * inv + bb.y + qq.y;
    r.z = a0.z * inv + bb.z + qq.z;
    r.w = a0.w * inv + bb.w + qq.w;
    if (RELU) {
        r.x = fmaxf(r.x, 0.f); r.y = fmaxf(r.y, 0.f);
        r.z = fmaxf(r.z, 0.f); r.w = fmaxf(r.w, 0.f);
    }
    *(float4*)(out + (size_t)v * D + tx * 4) = r;
}

// ---------------- launch ----------------
extern "C" void kernel_launch(void* const* d_in, const int* in_sizes, int n_in,
                              void* d_out, int out_size) {
    const float* x    = (const float*)d_in[0];
    const void*  ei   = d_in[1];
    const float* w1_l = (const float*)d_in[2];
    const float* b1   = (const float*)d_in[3];
    const float* w1_r = (const float*)d_in[4];
    const float* w2_l = (const float*)d_in[5];
    const float* b2   = (const float*)d_in[6];
    const float* w2_r = (const float*)d_in[7];
    float*       out  = (float*)d_out;

    const int E = in_sizes[1] / 2;
    const int N = in_sizes[0] / 128;

    static cudaStream_t s_side = nullptr;
    static cudaEvent_t ev_fork = nullptr, ev_csr = nullptr, ev_g1 = nullptr,
                       ev_a1A = nullptr, ev_a1B = nullptr;
    if (!s_side) {
        cudaStreamCreateWithFlags(&s_side, cudaStreamNonBlocking);
        cudaEventCreateWithFlags(&ev_fork, cudaEventDisableTiming);
        cudaEventCreateWithFlags(&ev_csr,  cudaEventDisableTiming);
        cudaEventCreateWithFlags(&ev_g1,   cudaEventDisableTiming);
        cudaEventCreateWithFlags(&ev_a1A,  cudaEventDisableTiming);
        cudaEventCreateWithFlags(&ev_a1B,  cudaEventDisableTiming);
    }

    int *flag, *deg, *off, *cur, *csr;
    float *p1, *q1, *h, *p2, *q2;
    cudaGetSymbolAddress((void**)&flag, g_is32);
    cudaGetSymbolAddress((void**)&deg, g_deg);
    cudaGetSymbolAddress((void**)&off, g_off);
    cudaGetSymbolAddress((void**)&cur, g_cur);
    cudaGetSymbolAddress((void**)&csr, g_csr);
    cudaGetSymbolAddress((void**)&p1, g_p1);
    cudaGetSymbolAddress((void**)&q1, g_q1);
    cudaGetSymbolAddress((void**)&h,  g_h);
    cudaGetSymbolAddress((void**)&p2, g_p2);
    cudaGetSymbolAddress((void**)&q2, g_q2);

    const int smem1 = (2 * 128 * 136 + 2 * 256 * 136) * 2;  // 208896
    const int smem2 = (2 * 128 * 136 + 2 * 128 * 136) * 2;  // 139264
    cudaFuncSetAttribute((const void*)mma_gemm<128>,
                         cudaFuncAttributeMaxDynamicSharedMemorySize, smem1);
    cudaFuncSetAttribute((const void*)mma_gemm<64>,
                         cudaFuncAttributeMaxDynamicSharedMemorySize, smem2);

    const int tiles = (N + 127) / 128;

    // ---- fork: CSR chain on side stream, GEMM1 on main ----
    cudaEventRecord(ev_fork, 0);
    cudaStreamWaitEvent(s_side, ev_fork, 0);

    cudaMemsetAsync(flag, 0, sizeof(int), s_side);
    cudaMemsetAsync(deg, 0, (size_t)N * sizeof(int), s_side);
    probe_kernel<<<256, 256, 0, s_side>>>((const long long*)ei, E, N, flag);
    hist_kernel<<<(E + 255) / 256, 256, 0, s_side>>>(ei, E, N, deg);
    scan_kernel<<<1, 1024, 0, s_side>>>(deg, off, cur, N);
    scatter_kernel<<<(E + 255) / 256, 256, 0, s_side>>>(ei, E, N, cur, csr);

    mma_gemm<128><<<tiles, 512, smem1>>>(x, w1_l, w1_r, p1, q1, N);
    cudaEventRecord(ev_g1, 0);

    // ---- agg1 in two chunks on side stream (CSR already ordered there) ----
    const int NA = 32768;                 // chunk A: 256 tiles
    const int tilesA = NA / 128;
    cudaStreamWaitEvent(s_side, ev_g1, 0);
    {
        dim3 blk(32, 8);
        agg_kernel<128, true><<<(NA + 7) / 8, blk, 0, s_side>>>(
            p1, q1, b1, off, csr, h, 0, NA);
        cudaEventRecord(ev_a1A, s_side);
        agg_kernel<128, true><<<(N - NA + 7) / 8, blk, 0, s_side>>>(
            p1, q1, b1, off, csr, h, NA, N);
        cudaEventRecord(ev_a1B, s_side);
    }

    // ---- GEMM2 chunk A overlaps agg1 chunk B ----
    cudaStreamWaitEvent(0, ev_a1A, 0);
    mma_gemm<64><<<tilesA, 512, smem2>>>(h, w2_l, w2_r, p2, q2, NA);
    cudaStreamWaitEvent(0, ev_a1B, 0);
    mma_gemm<64><<<tiles - tilesA, 512, smem2>>>(
        h + (size_t)NA * 128, w2_l, w2_r,
        p2 + (size_t)NA * 64, q2 + (size_t)NA * 64, N - NA);

    // ---- agg2 ----
    {
        dim3 blk(16, 16);
        agg_kernel<64, false><<<(N + 15) / 16, blk>>>(p2, q2, b2, off, csr, out, 0, N);
    }
}

// round 7
// speedup vs baseline: 1.0246x; 1.0246x over previous
#include <cuda_runtime.h>
#include <cuda_bf16.h>
#include <cstdint>

#define NN 50000
#define EE 600000

// ---------------- scratch ----------------
__device__ int   g_is32;
__device__ int   g_deg[NN];
__device__ int   g_off[NN + 1];
__device__ int   g_cur[NN];
__device__ int   g_csr[EE];
__device__ float g_p1[(size_t)NN * 128];
__device__ float g_q1[(size_t)NN * 128];
__device__ float g_h [(size_t)NN * 128];
__device__ float g_p2[(size_t)NN * 64];
__device__ float g_q2[(size_t)NN * 64];

// ---------------- dtype probe (+deg zeroing) + CSR ----------------
__global__ void probe_kernel(const long long* __restrict__ ei, int count, int N,
                             int* __restrict__ flag, int* __restrict__ deg) {
    int i = blockIdx.x * blockDim.x + threadIdx.x;
    int stride = gridDim.x * blockDim.x;
    for (int j = i; j < N; j += stride) deg[j] = 0;
    bool bad = false;
    for (int j = i; j < count; j += stride) {
        long long v = ei[j];
        bad |= (v < 0 || v >= (long long)N);
    }
    if (__any_sync(0xFFFFFFFF, bad) && (threadIdx.x & 31) == 0)
        *flag = 1;
}
__device__ __forceinline__ int load_idx(const void* ei, int pos, int is32) {
    if (is32) return ((const int*)ei)[pos];
    return (int)((const long long*)ei)[pos];
}
__global__ void hist_kernel(const void* __restrict__ ei, int E, int N,
                            int* __restrict__ deg) {
    int i = blockIdx.x * blockDim.x + threadIdx.x;
    if (i >= E) return;
    int d = load_idx(ei, E + i, g_is32);
    if ((unsigned)d < (unsigned)N) atomicAdd(&deg[d], 1);
}
__global__ void scan_kernel(const int* __restrict__ deg, int* __restrict__ off,
                            int* __restrict__ cur, int n) {
    __shared__ int part[1024];
    int t = threadIdx.x;
    int chunk = (n + 1023) / 1024;
    int begin = t * chunk, end = begin + chunk;
    if (end > n) end = n;
    int s = 0;
    for (int i = begin; i < end; i++) s += deg[i];
    part[t] = s;
    __syncthreads();
    for (int d = 1; d < 1024; d <<= 1) {
        int v = (t >= d) ? part[t - d] : 0;
        __syncthreads();
        part[t] += v;
        __syncthreads();
    }
    int run = (t == 0) ? 0 : part[t - 1];
    for (int i = begin; i < end; i++) { off[i] = run; cur[i] = run; run += deg[i]; }
    if (t == 1023) off[n] = part[1023];
}
__global__ void scatter_kernel(const void* __restrict__ ei, int E, int N,
                               int* __restrict__ cur, int* __restrict__ csr) {
    int i = blockIdx.x * blockDim.x + threadIdx.x;
    if (i >= E) return;
    int is32 = g_is32;
    int s = load_idx(ei, i, is32);
    int d = load_idx(ei, E + i, is32);
    if ((unsigned)d >= (unsigned)N || (unsigned)s >= (unsigned)N) return;
    int pos = atomicAdd(&cur[d], 1);
    if ((unsigned)pos < (unsigned)EE) csr[pos] = s;
}

// ---------------- mma.sync helpers ----------------
__device__ __forceinline__ uint32_t smem_u32(const void* p) {
    uint32_t a;
    asm("{ .reg .u64 t; cvta.to.shared.u64 t, %1; cvt.u32.u64 %0, t; }" : "=r"(a) : "l"(p));
    return a;
}
#define LDSM_X4(r0, r1, r2, r3, addr)                                          \
    asm volatile("ldmatrix.sync.aligned.m8n8.x4.shared.b16 {%0,%1,%2,%3}, [%4];" \
                 : "=r"(r0), "=r"(r1), "=r"(r2), "=r"(r3) : "r"(addr))
#define MMA16816(d, a, b)                                                      \
    asm volatile("mma.sync.aligned.m16n8k16.row.col.f32.bf16.bf16.f32 "        \
                 "{%0,%1,%2,%3}, {%4,%5,%6,%7}, {%8,%9}, {%0,%1,%2,%3};"       \
                 : "+f"((d)[0]), "+f"((d)[1]), "+f"((d)[2]), "+f"((d)[3])       \
                 : "r"((a)[0]), "r"((a)[1]), "r"((a)[2]), "r"((a)[3]),          \
                   "r"((b)[0]), "r"((b)[1]))

__device__ __forceinline__ void split_bf16(float v, __nv_bfloat16& hi, __nv_bfloat16& lo) {
    hi = __float2bfloat16(v);
    lo = __float2bfloat16(v - __bfloat162float(hi));
}

// ---------------- dual GEMM: out0 = A@W0, out1 = A@W1 ----------------
// 3-pass bf16 split: D = Ah*Bh + Ah*Bl + Al*Bh  (fp32 accum).
template <int NCOL>
__global__ void __launch_bounds__(512, 1)
mma_gemm(const float* __restrict__ A, const float* __restrict__ W0,
         const float* __restrict__ W1, float* __restrict__ out0,
         float* __restrict__ out1, int M) {
    constexpr int NT   = 2 * NCOL;
    constexpr int LDK  = 136;
    constexpr int A_H  = 0;
    constexpr int A_L  = 128 * LDK;
    constexpr int B_H  = 2 * 128 * LDK;
    constexpr int B_L  = B_H + NT * LDK;
    constexpr int WC   = NT / 4;
    constexpr int NTL  = WC / 8;

    extern __shared__ __nv_bfloat16 sm[];
    const uint32_t sbase = smem_u32(sm);
    const int tid  = threadIdx.x;
    const int wid  = tid >> 5, lane = tid & 31;
    const int brow = blockIdx.x * 128;

    for (int i = tid; i < 128 * 32; i += 512) {
        int row = i >> 5, c4 = (i & 31) << 2;
        float4 v = make_float4(0.f, 0.f, 0.f, 0.f);
        if (brow + row < M)
            v = *(const float4*)(A + (size_t)(brow + row) * 128 + c4);
        __nv_bfloat16 h0, l0, h1, l1, h2, l2, h3, l3;
        split_bf16(v.x, h0, l0); split_bf16(v.y, h1, l1);
        split_bf16(v.z, h2, l2); split_bf16(v.w, h3, l3);
        int o = row * LDK + c4;
        *(__nv_bfloat162*)(sm + A_H + o)     = __nv_bfloat162(h0, h1);
        *(__nv_bfloat162*)(sm + A_H + o + 2) = __nv_bfloat162(h2, h3);
        *(__nv_bfloat162*)(sm + A_L + o)     = __nv_bfloat162(l0, l1);
        *(__nv_bfloat162*)(sm + A_L + o + 2) = __nv_bfloat162(l2, l3);
    }
    for (int i = tid; i < NT * 128; i += 512) {
        int k = i / NT, n = i % NT;
        float v = (n < NCOL) ? W0[k * NCOL + n] : W1[k * NCOL + (n - NCOL)];
        __nv_bfloat16 h, l;
        split_bf16(v, h, l);
        sm[B_H + n * LDK + k] = h;
        sm[B_L + n * LDK + k] = l;
    }
    __syncthreads();

    const int r0 = (wid >> 2) * 32;
    const int c0 = (wid & 3) * WC;
    const uint32_t frag_off = (uint32_t)((lane & 15) * LDK + (lane >> 4) * 8) * 2;

    float acc[2][NTL][4];
#pragma unroll
    for (int mt = 0; mt < 2; mt++)
#pragma unroll
        for (int nt = 0; nt < NTL; nt++)
#pragma unroll
            for (int j = 0; j < 4; j++) acc[mt][nt][j] = 0.f;

    const int APASS[3] = {A_H, A_H, A_L};
    const int BPASS[3] = {B_H, B_L, B_H};
#pragma unroll
    for (int pass = 0; pass < 3; pass++) {
        const uint32_t abase = sbase + (uint32_t)APASS[pass] * 2 + frag_off;
        const uint32_t bbase = sbase + (uint32_t)BPASS[pass] * 2 + frag_off;
#pragma unroll
        for (int ks = 0; ks < 8; ks++) {
            uint32_t a[2][4];
#pragma unroll
            for (int mt = 0; mt < 2; mt++)
                LDSM_X4(a[mt][0], a[mt][1], a[mt][2], a[mt][3],
                        abase + (uint32_t)((r0 + mt * 16) * LDK + ks * 16) * 2);
            uint32_t b[NTL][2];
#pragma unroll
            for (int np = 0; np < NTL / 2; np++) {
                uint32_t q0, q1, q2, q3;
                LDSM_X4(q0, q1, q2, q3,
                        bbase + (uint32_t)((c0 + np * 16) * LDK + ks * 16) * 2);
                b[2 * np][0] = q0; b[2 * np][1] = q2;
                b[2 * np + 1][0] = q1; b[2 * np + 1][1] = q3;
            }
#pragma unroll
            for (int mt = 0; mt < 2; mt++)
#pragma unroll
                for (int nt = 0; nt < NTL; nt++)
                    MMA16816(acc[mt][nt], a[mt], b[nt]);
        }
    }

    float* dst = (c0 < NCOL) ? out0 : out1;
    const int ncoff = (c0 < NCOL) ? c0 : (c0 - NCOL);
#pragma unroll
    for (int mt = 0; mt < 2; mt++) {
        int rlo = brow + r0 + mt * 16 + (lane >> 2);
        int rhi = rlo + 8;
#pragma unroll
        for (int nt = 0; nt < NTL; nt++) {
            int col = ncoff + nt * 8 + (lane & 3) * 2;
            if (rlo < M)
                *(float2*)(dst + (size_t)rlo * NCOL + col) =
                    make_float2(acc[mt][nt][0], acc[mt][nt][1]);
            if (rhi < M)
                *(float2*)(dst + (size_t)rhi * NCOL + col) =
                    make_float2(acc[mt][nt][2], acc[mt][nt][3]);
        }
    }
}

// ---------------- aggregation: float4, 4-way unrolled ----------------
template <int D, bool RELU>
__global__ void agg_kernel(const float* __restrict__ p, const float* __restrict__ q,
                           const float* __restrict__ bias,
                           const int* __restrict__ off, const int* __restrict__ csr,
                           float* __restrict__ out, int n) {
    const int tx = threadIdx.x;             // [0, D/4)
    const int v = blockIdx.x * blockDim.y + threadIdx.y;
    if (v >= n) return;
    const int s = off[v], e = off[v + 1];

    float4 a0 = make_float4(0.f, 0.f, 0.f, 0.f);
    float4 a1 = make_float4(0.f, 0.f, 0.f, 0.f);
    float4 a2 = make_float4(0.f, 0.f, 0.f, 0.f);
    float4 a3 = make_float4(0.f, 0.f, 0.f, 0.f);
    int i = s;
    for (; i + 4 <= e; i += 4) {
        int u0 = __ldg(&csr[i]),     u1 = __ldg(&csr[i + 1]);
        int u2 = __ldg(&csr[i + 2]), u3 = __ldg(&csr[i + 3]);
        float4 x0 = *(const float4*)(p + (size_t)u0 * D + tx * 4);
        float4 x1 = *(const float4*)(p + (size_t)u1 * D + tx * 4);
        float4 x2 = *(const float4*)(p + (size_t)u2 * D + tx * 4);
        float4 x3 = *(const float4*)(p + (size_t)u3 * D + tx * 4);
        a0.x += x0.x; a0.y += x0.y; a0.z += x0.z; a0.w += x0.w;
        a1.x += x1.x; a1.y += x1.y; a1.z += x1.z; a1.w += x1.w;
        a2.x += x2.x; a2.y += x2.y; a2.z += x2.z; a2.w += x2.w;
        a3.x += x3.x; a3.y += x3.y; a3.z += x3.z; a3.w += x3.w;
    }
    for (; i < e; i++) {
        int u0 = __ldg(&csr[i]);
        float4 x0 = *(const float4*)(p + (size_t)u0 * D + tx * 4);
        a0.x += x0.x; a0.y += x0.y; a0.z += x0.z; a0.w += x0.w;
    }
    a0.x += a1.x + a2.x + a3.x;
    a0.y += a1.y + a2.y + a3.y;
    a0.z += a1.z + a2.z + a3.z;
    a0.w += a1.w + a2.w + a3.w;

    const float inv = (e > s) ? 1.f / (float)(e - s) : 0.f;
    float4 bb = *(const float4*)(bias + tx * 4);
    float4 qq = *(const float4*)(q + (size_t)v * D + tx * 4);
    float4 r;
    r.x = a0.x * inv + bb.x + qq.x;
    r.y = a0.y * inv + bb.y + qq.y;
    r.z = a0.z * inv + bb.z + qq.z;
    r.w = a0.w * inv + bb.w + qq.w;
    if (RELU) {
        r.x = fmaxf(r.x, 0.f); r.y = fmaxf(r.y, 0.f);
        r.z = fmaxf(r.z, 0.f); r.w = fmaxf(r.w, 0.f);
    }
    *(float4*)(out + (size_t)v * D + tx * 4) = r;
}

// ---------------- launch ----------------
extern "C" void kernel_launch(void* const* d_in, const int* in_sizes, int n_in,
                              void* d_out, int out_size) {
    const float* x    = (const float*)d_in[0];
    const void*  ei   = d_in[1];
    const float* w1_l = (const float*)d_in[2];
    const float* b1   = (const float*)d_in[3];
    const float* w1_r = (const float*)d_in[4];
    const float* w2_l = (const float*)d_in[5];
    const float* b2   = (const float*)d_in[6];
    const float* w2_r = (const float*)d_in[7];
    float*       out  = (float*)d_out;

    const int E = in_sizes[1] / 2;
    const int N = in_sizes[0] / 128;

    static cudaStream_t s_side = nullptr;
    static cudaEvent_t ev_fork = nullptr, ev_csr = nullptr;
    if (!s_side) {
        cudaStreamCreateWithFlags(&s_side, cudaStreamNonBlocking);
        cudaEventCreateWithFlags(&ev_fork, cudaEventDisableTiming);
        cudaEventCreateWithFlags(&ev_csr,  cudaEventDisableTiming);
    }

    int *flag, *deg, *off, *cur, *csr;
    float *p1, *q1, *h, *p2, *q2;
    cudaGetSymbolAddress((void**)&flag, g_is32);
    cudaGetSymbolAddress((void**)&deg, g_deg);
    cudaGetSymbolAddress((void**)&off, g_off);
    cudaGetSymbolAddress((void**)&cur, g_cur);
    cudaGetSymbolAddress((void**)&csr, g_csr);
    cudaGetSymbolAddress((void**)&p1, g_p1);
    cudaGetSymbolAddress((void**)&q1, g_q1);
    cudaGetSymbolAddress((void**)&h,  g_h);
    cudaGetSymbolAddress((void**)&p2, g_p2);
    cudaGetSymbolAddress((void**)&q2, g_q2);

    const int smem1 = (2 * 128 * 136 + 2 * 256 * 136) * 2;  // 208896
    const int smem2 = (2 * 128 * 136 + 2 * 128 * 136) * 2;  // 139264
    cudaFuncSetAttribute((const void*)mma_gemm<128>,
                         cudaFuncAttributeMaxDynamicSharedMemorySize, smem1);
    cudaFuncSetAttribute((const void*)mma_gemm<64>,
                         cudaFuncAttributeMaxDynamicSharedMemorySize, smem2);

    const int tiles = (N + 127) / 128;

    // ---- fork: CSR chain on side stream ----
    // capture order: memset(1) probe(2) hist(3) scan(4) scatter(5) gemm1(6) ...
    // ncu -s 5 -c 1 profiles launch #6 = mma_gemm<128>.
    cudaEventRecord(ev_fork, 0);
    cudaStreamWaitEvent(s_side, ev_fork, 0);

    cudaMemsetAsync(flag, 0, sizeof(int), s_side);
    probe_kernel<<<(E + 255) / 256, 256, 0, s_side>>>(
        (const long long*)ei, E, N, flag, deg);
    hist_kernel<<<(E + 255) / 256, 256, 0, s_side>>>(ei, E, N, deg);
    scan_kernel<<<1, 1024, 0, s_side>>>(deg, off, cur, N);
    scatter_kernel<<<(E + 255) / 256, 256, 0, s_side>>>(ei, E, N, cur, csr);
    cudaEventRecord(ev_csr, s_side);

    // ---- layer 1 GEMM (concurrent with CSR chain) ----
    mma_gemm<128><<<tiles, 512, smem1>>>(x, w1_l, w1_r, p1, q1, N);

    // ---- join ----
    cudaStreamWaitEvent(0, ev_csr, 0);

    // ---- layer 1 agg ----
    {
        dim3 blk(32, 8);
        agg_kernel<128, true><<<(N + 7) / 8, blk>>>(p1, q1, b1, off, csr, h, N);
    }

    // ---- layer 2 ----
    mma_gemm<64><<<tiles, 512, smem2>>>(h, w2_l, w2_r, p2, q2, N);
    {
        dim3 blk(16, 16);
        agg_kernel<64, false><<<(N + 15) / 16, blk>>>(p2, q2, b2, off, csr, out, N);
    }
}